// round 10
// baseline (speedup 1.0000x reference)
#include <cuda_runtime.h>

#define DM   2048     // d_model
#define DL   512      // d_latent
#define NH   16
#define HD   128
#define SEQ  2048
#define NB   2
#define TOK  (NB*SEQ) // 4096

typedef unsigned int uint32;

// ---- tf32 mma helpers (layout verified in R6) ----
__device__ __forceinline__ uint32 f2tf32(float f) {
    uint32 u;
    asm("cvt.rna.tf32.f32 %0, %1;" : "=r"(u) : "f"(f));
    return u;
}
__device__ __forceinline__ void mma_tf32(float* d, const uint32* a, const uint32* b) {
    asm volatile(
        "mma.sync.aligned.m16n8k8.row.col.f32.tf32.tf32.f32 "
        "{%0,%1,%2,%3}, {%4,%5,%6,%7}, {%8,%9}, {%0,%1,%2,%3};"
        : "+f"(d[0]), "+f"(d[1]), "+f"(d[2]), "+f"(d[3])
        : "r"(a[0]), "r"(a[1]), "r"(a[2]), "r"(a[3]), "r"(b[0]), "r"(b[1]));
}

// Scratch (allocation-free rule: __device__ globals, device-code refs only)
__device__ float g_q  [TOK*DM];
__device__ float g_ckv[TOK*DL];
__device__ float g_k  [TOK*DM];
__device__ float g_v  [TOK*DM];
__device__ float g_ctx[TOK*DM];

// ---------------------------------------------------------------------------
// C[M,N] = A[M,K] @ B[N,K]^T  (+ optional bias[N]) via tf32 mma.
// 128x128 tile, BK=16, 256 threads (8 warps), warp tile 32x64.
// DOUBLE-BUFFERED in STATIC smem (40KB total): one __syncthreads per K-tile;
// stores for tile i+1 overlap mma of tile i.
// Pitch GP2=20: fragment-load bank = (20g+t) mod 32 -> all 32 distinct.
// ---------------------------------------------------------------------------
#define GP2 20   // smem pitch (floats)

template<int MODE>
__global__ __launch_bounds__(256) void tgemm_nt(
    const float* __restrict__ Aarg, const float* __restrict__ B,
    const float* __restrict__ bias, float* __restrict__ Carg,
    int M, int N, int K)
{
    const float* A;
    float* C;
    if      (MODE == 0) { A = Aarg;  C = g_ckv; }
    else if (MODE == 1) { A = Aarg;  C = g_q;   }
    else if (MODE == 2) { A = g_ckv; C = g_k;   }
    else if (MODE == 3) { A = g_ckv; C = g_v;   }
    else                { A = g_ctx; C = Carg;  }

    __shared__ float sA[2][128][GP2];
    __shared__ float sB[2][128][GP2];

    const int tid  = threadIdx.x;
    const int lane = tid & 31;
    const int w    = tid >> 5;
    const int g    = lane >> 2;
    const int t    = lane & 3;
    const int wm   = w & 3;
    const int wn   = w >> 2;
    const int row0 = blockIdx.y * 128;
    const int col0 = blockIdx.x * 128;

    // loader: 2 threads per row, 8 cols (2 float4) each
    const int lr  = tid >> 1;
    const int lko = (tid & 1) * 8;

    float acc[2][8][4];
#pragma unroll
    for (int mt = 0; mt < 2; mt++)
#pragma unroll
        for (int nt = 0; nt < 8; nt++)
#pragma unroll
            for (int r = 0; r < 4; r++) acc[mt][nt][r] = 0.f;

    const int nTiles = K >> 4;

    // ---- preamble: tile 0 into buffer 0 ----
    float4 pa[2], pb[2];
#pragma unroll
    for (int i = 0; i < 2; i++) {
        pa[i] = *(const float4*)(A + (size_t)(row0 + lr) * K + lko + i * 4);
        pb[i] = *(const float4*)(B + (size_t)(col0 + lr) * K + lko + i * 4);
    }
#pragma unroll
    for (int i = 0; i < 2; i++) {
        float4 ca, cb;
        ca.x = __uint_as_float(f2tf32(pa[i].x)); ca.y = __uint_as_float(f2tf32(pa[i].y));
        ca.z = __uint_as_float(f2tf32(pa[i].z)); ca.w = __uint_as_float(f2tf32(pa[i].w));
        cb.x = __uint_as_float(f2tf32(pb[i].x)); cb.y = __uint_as_float(f2tf32(pb[i].y));
        cb.z = __uint_as_float(f2tf32(pb[i].z)); cb.w = __uint_as_float(f2tf32(pb[i].w));
        *(float4*)&sA[0][lr][lko + i * 4] = ca;
        *(float4*)&sB[0][lr][lko + i * 4] = cb;
    }
    __syncthreads();

    for (int it = 0; it < nTiles; it++) {
        const int cur = it & 1;

        // prefetch next tile from global (hidden under mma)
        if (it + 1 < nTiles) {
            const int kn = (it + 1) << 4;
#pragma unroll
            for (int i = 0; i < 2; i++) {
                pa[i] = *(const float4*)(A + (size_t)(row0 + lr) * K + kn + lko + i * 4);
                pb[i] = *(const float4*)(B + (size_t)(col0 + lr) * K + kn + lko + i * 4);
            }
        }

        // ---- mma over current buffer (2 k-steps of 8) ----
#pragma unroll
        for (int s = 0; s < 2; s++) {
            const int kb = s * 8 + t;
            uint32 af[2][4], bf[8][2];
#pragma unroll
            for (int mt = 0; mt < 2; mt++) {
                const int rb = wm * 32 + mt * 16;
                af[mt][0] = __float_as_uint(sA[cur][rb + g    ][kb]);
                af[mt][1] = __float_as_uint(sA[cur][rb + 8 + g][kb]);
                af[mt][2] = __float_as_uint(sA[cur][rb + g    ][kb + 4]);
                af[mt][3] = __float_as_uint(sA[cur][rb + 8 + g][kb + 4]);
            }
#pragma unroll
            for (int nt = 0; nt < 8; nt++) {
                const int nb = wn * 64 + nt * 8 + g;
                bf[nt][0] = __float_as_uint(sB[cur][nb][kb]);
                bf[nt][1] = __float_as_uint(sB[cur][nb][kb + 4]);
            }
#pragma unroll
            for (int mt = 0; mt < 2; mt++)
#pragma unroll
                for (int nt = 0; nt < 8; nt++)
                    mma_tf32(acc[mt][nt], af[mt], bf[nt]);
        }

        // ---- convert + store next tile into alternate buffer ----
        if (it + 1 < nTiles) {
            const int nxt = cur ^ 1;
#pragma unroll
            for (int i = 0; i < 2; i++) {
                float4 ca, cb;
                ca.x = __uint_as_float(f2tf32(pa[i].x)); ca.y = __uint_as_float(f2tf32(pa[i].y));
                ca.z = __uint_as_float(f2tf32(pa[i].z)); ca.w = __uint_as_float(f2tf32(pa[i].w));
                cb.x = __uint_as_float(f2tf32(pb[i].x)); cb.y = __uint_as_float(f2tf32(pb[i].y));
                cb.z = __uint_as_float(f2tf32(pb[i].z)); cb.w = __uint_as_float(f2tf32(pb[i].w));
                *(float4*)&sA[nxt][lr][lko + i * 4] = ca;
                *(float4*)&sB[nxt][lr][lko + i * 4] = cb;
            }
        }
        __syncthreads();
    }

    // ---- epilogue ----
#pragma unroll
    for (int mt = 0; mt < 2; mt++) {
        const int ra = row0 + wm * 32 + mt * 16 + g;
#pragma unroll
        for (int nt = 0; nt < 8; nt++) {
            const int cb = col0 + wn * 64 + nt * 8 + 2 * t;
            float b0 = 0.f, b1 = 0.f;
            if (MODE == 4) { b0 = bias[cb]; b1 = bias[cb + 1]; }
            float2 v0 = make_float2(acc[mt][nt][0] + b0, acc[mt][nt][1] + b1);
            float2 v1 = make_float2(acc[mt][nt][2] + b0, acc[mt][nt][3] + b1);
            *(float2*)(C + (size_t)ra * N + cb)       = v0;
            *(float2*)(C + (size_t)(ra + 8) * N + cb) = v1;
        }
    }
}

// ---------------------------------------------------------------------------
// Flash attention via tf32 mma (R7, proven).
// ---------------------------------------------------------------------------
#define AQ_P 132
#define AK_P 132
#define AV_P 136
#define AP_P 68
#define SM_AQ 0
#define SM_AK (SM_AQ + 128*AQ_P)
#define SM_AV (SM_AK + 64*AK_P)
#define SM_AP (SM_AV + 64*AV_P)
#define ATTN_FLOATS (SM_AP + 128*AP_P)
#define ATTN_SMEM_BYTES (ATTN_FLOATS * 4)  // 171008

__global__ __launch_bounds__(256, 1) void attn_mma()
{
    extern __shared__ float sm[];
    float* Qs = sm + SM_AQ;
    float* Ks = sm + SM_AK;
    float* Vs = sm + SM_AV;
    float* Ps = sm + SM_AP;

    const int tid  = threadIdx.x;
    const int lane = tid & 31;
    const int w    = tid >> 5;
    const int g    = lane >> 2;
    const int t    = lane & 3;
    const int bx   = gridDim.x - 1 - blockIdx.x;
    const int bh   = blockIdx.y;
    const int b    = bh >> 4;
    const int h    = bh & 15;
    const int q0   = bx * 128;
    const int r0   = w * 16;

    const float scale = 0.08838834764831845f;

    {
        int row = tid >> 1;
        int cb  = (tid & 1) * 64;
        const float* src = g_q + (size_t)(b*SEQ + q0 + row) * DM + h*HD + cb;
        float* dst = Qs + row * AQ_P + cb;
#pragma unroll
        for (int i = 0; i < 16; i++) {
            float4 v = *(const float4*)(src + i * 4);
            dst[i*4+0] = __uint_as_float(f2tf32(v.x * scale));
            dst[i*4+1] = __uint_as_float(f2tf32(v.y * scale));
            dst[i*4+2] = __uint_as_float(f2tf32(v.z * scale));
            dst[i*4+3] = __uint_as_float(f2tf32(v.w * scale));
        }
    }

    float oacc[16][4];
#pragma unroll
    for (int nt = 0; nt < 16; nt++)
#pragma unroll
        for (int r = 0; r < 4; r++) oacc[nt][r] = 0.f;
    float mA = -1e30f, mB = -1e30f, lA = 0.f, lB = 0.f;

    const int nkt = (q0 + 128) / 64;
    for (int kt = 0; kt < nkt; kt++) {
        const int k0 = kt * 64;
        __syncthreads();

        {
            int row = tid >> 2;
            int cb  = (tid & 3) * 32;
            const float* ksrc = g_k + (size_t)(b*SEQ + k0 + row) * DM + h*HD + cb;
            const float* vsrc = g_v + (size_t)(b*SEQ + k0 + row) * DM + h*HD + cb;
            float* kdst = Ks + row * AK_P + cb;
            float* vdst = Vs + row * AV_P + cb;
#pragma unroll
            for (int i = 0; i < 8; i++) {
                float4 kv = *(const float4*)(ksrc + i * 4);
                kdst[i*4+0] = __uint_as_float(f2tf32(kv.x));
                kdst[i*4+1] = __uint_as_float(f2tf32(kv.y));
                kdst[i*4+2] = __uint_as_float(f2tf32(kv.z));
                kdst[i*4+3] = __uint_as_float(f2tf32(kv.w));
                float4 vv = *(const float4*)(vsrc + i * 4);
                vdst[i*4+0] = __uint_as_float(f2tf32(vv.x));
                vdst[i*4+1] = __uint_as_float(f2tf32(vv.y));
                vdst[i*4+2] = __uint_as_float(f2tf32(vv.z));
                vdst[i*4+3] = __uint_as_float(f2tf32(vv.w));
            }
        }
        __syncthreads();

        float sacc[8][4];
#pragma unroll
        for (int nt = 0; nt < 8; nt++)
#pragma unroll
            for (int r = 0; r < 4; r++) sacc[nt][r] = 0.f;

#pragma unroll
        for (int s = 0; s < 16; s++) {
            const int kb = s * 8 + t;
            uint32 af[4];
            af[0] = __float_as_uint(Qs[(r0 + g    ) * AQ_P + kb]);
            af[1] = __float_as_uint(Qs[(r0 + 8 + g) * AQ_P + kb]);
            af[2] = __float_as_uint(Qs[(r0 + g    ) * AQ_P + kb + 4]);
            af[3] = __float_as_uint(Qs[(r0 + 8 + g) * AQ_P + kb + 4]);
#pragma unroll
            for (int nt = 0; nt < 8; nt++) {
                uint32 bf[2];
                bf[0] = __float_as_uint(Ks[(nt*8 + g) * AK_P + kb]);
                bf[1] = __float_as_uint(Ks[(nt*8 + g) * AK_P + kb + 4]);
                mma_tf32(sacc[nt], af, bf);
            }
        }

        if (k0 + 63 > q0 + r0) {
            const int rowA = q0 + r0 + g;
            const int rowB = rowA + 8;
#pragma unroll
            for (int nt = 0; nt < 8; nt++) {
                const int col = k0 + nt*8 + 2*t;
                if (col     > rowA) sacc[nt][0] = -1e30f;
                if (col + 1 > rowA) sacc[nt][1] = -1e30f;
                if (col     > rowB) sacc[nt][2] = -1e30f;
                if (col + 1 > rowB) sacc[nt][3] = -1e30f;
            }
        }

        float mxA = -1e30f, mxB = -1e30f;
#pragma unroll
        for (int nt = 0; nt < 8; nt++) {
            mxA = fmaxf(mxA, fmaxf(sacc[nt][0], sacc[nt][1]));
            mxB = fmaxf(mxB, fmaxf(sacc[nt][2], sacc[nt][3]));
        }
        mxA = fmaxf(mxA, __shfl_xor_sync(0xffffffffu, mxA, 1));
        mxA = fmaxf(mxA, __shfl_xor_sync(0xffffffffu, mxA, 2));
        mxB = fmaxf(mxB, __shfl_xor_sync(0xffffffffu, mxB, 1));
        mxB = fmaxf(mxB, __shfl_xor_sync(0xffffffffu, mxB, 2));

        const float mnA = fmaxf(mA, mxA);
        const float mnB = fmaxf(mB, mxB);
        const float corrA = __expf(mA - mnA);
        const float corrB = __expf(mB - mnB);

        float sumA = 0.f, sumB = 0.f;
        __syncwarp();
#pragma unroll
        for (int nt = 0; nt < 8; nt++) {
            float pA0 = __expf(sacc[nt][0] - mnA);
            float pA1 = __expf(sacc[nt][1] - mnA);
            float pB0 = __expf(sacc[nt][2] - mnB);
            float pB1 = __expf(sacc[nt][3] - mnB);
            sumA += pA0 + pA1;
            sumB += pB0 + pB1;
            float2 wa = make_float2(__uint_as_float(f2tf32(pA0)),
                                    __uint_as_float(f2tf32(pA1)));
            float2 wb = make_float2(__uint_as_float(f2tf32(pB0)),
                                    __uint_as_float(f2tf32(pB1)));
            *(float2*)(Ps + (r0 + g    ) * AP_P + nt*8 + 2*t) = wa;
            *(float2*)(Ps + (r0 + 8 + g) * AP_P + nt*8 + 2*t) = wb;
        }
        sumA += __shfl_xor_sync(0xffffffffu, sumA, 1);
        sumA += __shfl_xor_sync(0xffffffffu, sumA, 2);
        sumB += __shfl_xor_sync(0xffffffffu, sumB, 1);
        sumB += __shfl_xor_sync(0xffffffffu, sumB, 2);

        lA = lA * corrA + sumA;
        lB = lB * corrB + sumB;
        mA = mnA;
        mB = mnB;

#pragma unroll
        for (int nt = 0; nt < 16; nt++) {
            oacc[nt][0] *= corrA; oacc[nt][1] *= corrA;
            oacc[nt][2] *= corrB; oacc[nt][3] *= corrB;
        }
        __syncwarp();

#pragma unroll
        for (int s = 0; s < 8; s++) {
            const int kb = s * 8 + t;
            uint32 af[4];
            af[0] = __float_as_uint(Ps[(r0 + g    ) * AP_P + kb]);
            af[1] = __float_as_uint(Ps[(r0 + 8 + g) * AP_P + kb]);
            af[2] = __float_as_uint(Ps[(r0 + g    ) * AP_P + kb + 4]);
            af[3] = __float_as_uint(Ps[(r0 + 8 + g) * AP_P + kb + 4]);
#pragma unroll
            for (int nt = 0; nt < 16; nt++) {
                uint32 bf[2];
                bf[0] = __float_as_uint(Vs[(kb    ) * AV_P + nt*8 + g]);
                bf[1] = __float_as_uint(Vs[(kb + 4) * AV_P + nt*8 + g]);
                mma_tf32(oacc[nt], af, bf);
            }
        }
    }

    const float invA = 1.f / lA;
    const float invB = 1.f / lB;
    float* baseA = g_ctx + (size_t)(b*SEQ + q0 + r0 + g    ) * DM + h*HD;
    float* baseB = g_ctx + (size_t)(b*SEQ + q0 + r0 + 8 + g) * DM + h*HD;
#pragma unroll
    for (int nt = 0; nt < 16; nt++) {
        *(float2*)(baseA + nt*8 + 2*t) = make_float2(oacc[nt][0]*invA, oacc[nt][1]*invA);
        *(float2*)(baseB + nt*8 + 2*t) = make_float2(oacc[nt][2]*invB, oacc[nt][3]*invB);
    }
}

// ---------------------------------------------------------------------------
// Launch
// ---------------------------------------------------------------------------
extern "C" void kernel_launch(void* const* d_in, const int* in_sizes, int n_in,
                              void* d_out, int out_size)
{
    (void)in_sizes; (void)n_in; (void)out_size;
    const float* x    = (const float*)d_in[0];
    const float* W_q  = (const float*)d_in[1];
    const float* W_dkv= (const float*)d_in[2];
    const float* W_uk = (const float*)d_in[3];
    const float* W_uv = (const float*)d_in[4];
    const float* W_o  = (const float*)d_in[5];
    const float* W_b  = (const float*)d_in[6];
    float* out = (float*)d_out;

    cudaFuncSetAttribute(attn_mma,
                         cudaFuncAttributeMaxDynamicSharedMemorySize,
                         ATTN_SMEM_BYTES);

    dim3 blk(256);
    tgemm_nt<0><<<dim3(DL/128, TOK/128), blk>>>(x, W_dkv, nullptr, nullptr, TOK, DL, DM);
    tgemm_nt<1><<<dim3(DM/128, TOK/128), blk>>>(x, W_q, nullptr, nullptr, TOK, DM, DM);
    tgemm_nt<2><<<dim3(DM/128, TOK/128), blk>>>(nullptr, W_uk, nullptr, nullptr, TOK, DM, DL);
    tgemm_nt<3><<<dim3(DM/128, TOK/128), blk>>>(nullptr, W_uv, nullptr, nullptr, TOK, DM, DL);
    attn_mma<<<dim3(SEQ/128, NB*NH), dim3(256), ATTN_SMEM_BYTES>>>();
    tgemm_nt<4><<<dim3(DM/128, TOK/128), blk>>>(nullptr, W_o, W_b, out, TOK, DM, DM);
}

// round 11
// speedup vs baseline: 1.0070x; 1.0070x over previous
#include <cuda_runtime.h>

#define DM   2048     // d_model
#define DL   512      // d_latent
#define NH   16
#define HD   128
#define SEQ  2048
#define NB   2
#define TOK  (NB*SEQ) // 4096

typedef unsigned int uint32;

// ---- tf32 mma helpers (layout verified in R6) ----
__device__ __forceinline__ uint32 f2tf32(float f) {
    uint32 u;
    asm("cvt.rna.tf32.f32 %0, %1;" : "=r"(u) : "f"(f));
    return u;
}
__device__ __forceinline__ float f2tf32f(float f) {
    return __uint_as_float(f2tf32(f));
}
__device__ __forceinline__ void mma_tf32(float* d, const uint32* a, const uint32* b) {
    asm volatile(
        "mma.sync.aligned.m16n8k8.row.col.f32.tf32.tf32.f32 "
        "{%0,%1,%2,%3}, {%4,%5,%6,%7}, {%8,%9}, {%0,%1,%2,%3};"
        : "+f"(d[0]), "+f"(d[1]), "+f"(d[2]), "+f"(d[3])
        : "r"(a[0]), "r"(a[1]), "r"(a[2]), "r"(a[3]), "r"(b[0]), "r"(b[1]));
}

// Scratch (allocation-free rule: __device__ globals, device-code refs only)
__device__ float g_q  [TOK*DM];
__device__ float g_ckv[TOK*DL];
__device__ float g_k  [TOK*DM];
__device__ float g_v  [TOK*DM];
__device__ float g_ctx[TOK*DM];

// ---------------------------------------------------------------------------
// C[M,N] = A[M,K] @ B[N,K]^T  (+ optional bias[N]) via tf32 mma.
// 128x128 tile, BK=32, 256 threads (8 warps), warp tile 32x64.
// R7 control flow (single buffer, 2 syncs/tile) + PAIRED-K PERMUTED layout:
//   element k (gsel=k>>3, t''=k&7) stored at col gsel*8 + ((2*(t''&3) + (t''>>2)) ^ e(row))
//   with e(row) = ((row>>2)&3)<<1 (even XOR keeps (k,k+4) pairs adjacent).
// Fragment fetch becomes LDS.64: (k, k+4) in one load. Pitch 40 -> bank
// 8g + (2t^e): injective per 16-lane phase => conflict-free loads.
// Static smem: 2 x 128 x 40 x 4 = 41KB.
// ---------------------------------------------------------------------------
#define GPP 40   // smem pitch (floats)

template<int MODE>
__global__ __launch_bounds__(256) void tgemm_nt(
    const float* __restrict__ Aarg, const float* __restrict__ B,
    const float* __restrict__ bias, float* __restrict__ Carg,
    int M, int N, int K)
{
    const float* A;
    float* C;
    if      (MODE == 0) { A = Aarg;  C = g_ckv; }
    else if (MODE == 1) { A = Aarg;  C = g_q;   }
    else if (MODE == 2) { A = g_ckv; C = g_k;   }
    else if (MODE == 3) { A = g_ckv; C = g_v;   }
    else                { A = g_ctx; C = Carg;  }

    __shared__ float sA[128][GPP];
    __shared__ float sB[128][GPP];

    const int tid  = threadIdx.x;
    const int lane = tid & 31;
    const int w    = tid >> 5;
    const int g    = lane >> 2;
    const int t    = lane & 3;
    const int wm   = w & 3;
    const int wn   = w >> 2;
    const int row0 = blockIdx.y * 128;
    const int col0 = blockIdx.x * 128;

    // loader mapping: 2 threads per row, 16 consecutive k each
    const int lr   = tid >> 1;
    const int lko  = (tid & 1) * 16;
    const int grp0 = (tid & 1) * 2;             // lko >> 3
    const int er   = ((lr >> 2) & 3) << 1;      // store-side XOR

    // fragment-load XORs (row-dependent, rows rb+g / rb+8+g / B-rows)
    const int e1 = (g >> 2) << 1;               // rows rb+g   (rb mult of 16)
    const int e2 = ((2 + (g >> 2)) & 3) << 1;   // rows rb+8+g

    float acc[2][8][4];
#pragma unroll
    for (int mt = 0; mt < 2; mt++)
#pragma unroll
        for (int nt = 0; nt < 8; nt++)
#pragma unroll
            for (int r = 0; r < 4; r++) acc[mt][nt][r] = 0.f;

    // prefetch tile 0
    float4 pa[4], pb[4];
#pragma unroll
    for (int i = 0; i < 4; i++) {
        pa[i] = *(const float4*)(A + (size_t)(row0 + lr) * K + lko + i * 4);
        pb[i] = *(const float4*)(B + (size_t)(col0 + lr) * K + lko + i * 4);
    }

    for (int k0 = 0; k0 < K; k0 += 32) {
        __syncthreads();   // prior fragment reads done

        // ---- store staged tile with paired-k permutation ----
        {
            const float* fa = (const float*)pa;   // fa[k'] = k = lko + k'
            const float* fb = (const float*)pb;
#pragma unroll
            for (int a = 0; a < 2; a++) {
#pragma unroll
                for (int tp = 0; tp < 4; tp++) {
                    const int col = (grp0 + a) * 8 + ((2 * tp) ^ er);
                    float2 va = make_float2(f2tf32f(fa[8*a + tp]),
                                            f2tf32f(fa[8*a + tp + 4]));
                    float2 vb = make_float2(f2tf32f(fb[8*a + tp]),
                                            f2tf32f(fb[8*a + tp + 4]));
                    *(float2*)&sA[lr][col] = va;
                    *(float2*)&sB[lr][col] = vb;
                }
            }
        }
        __syncthreads();

        if (k0 + 32 < K) {
#pragma unroll
            for (int i = 0; i < 4; i++) {
                pa[i] = *(const float4*)(A + (size_t)(row0 + lr) * K + k0 + 32 + lko + i * 4);
                pb[i] = *(const float4*)(B + (size_t)(col0 + lr) * K + k0 + 32 + lko + i * 4);
            }
        }

        // ---- mma over current tile: 4 s-steps of k=8 ----
#pragma unroll
        for (int s = 0; s < 4; s++) {
            const int sb = s * 8;
            uint32 af[2][4], bf[8][2];
#pragma unroll
            for (int mt = 0; mt < 2; mt++) {
                const int rb = wm * 32 + mt * 16;
                float2 a1 = *(const float2*)&sA[rb + g    ][sb + ((2*t) ^ e1)];
                float2 a2 = *(const float2*)&sA[rb + 8 + g][sb + ((2*t) ^ e2)];
                af[mt][0] = __float_as_uint(a1.x);   // A[g][kb]
                af[mt][2] = __float_as_uint(a1.y);   // A[g][kb+4]
                af[mt][1] = __float_as_uint(a2.x);   // A[g+8][kb]
                af[mt][3] = __float_as_uint(a2.y);   // A[g+8][kb+4]
            }
#pragma unroll
            for (int nt = 0; nt < 8; nt++) {
                const int ebn = (((nt * 2) + (g >> 2)) & 3) << 1;
                float2 b1 = *(const float2*)&sB[wn*64 + nt*8 + g][sb + ((2*t) ^ ebn)];
                bf[nt][0] = __float_as_uint(b1.x);   // B[n][kb]
                bf[nt][1] = __float_as_uint(b1.y);   // B[n][kb+4]
            }
#pragma unroll
            for (int mt = 0; mt < 2; mt++)
#pragma unroll
                for (int nt = 0; nt < 8; nt++)
                    mma_tf32(acc[mt][nt], af[mt], bf[nt]);
        }
    }

    // ---- epilogue ----
#pragma unroll
    for (int mt = 0; mt < 2; mt++) {
        const int ra = row0 + wm * 32 + mt * 16 + g;
#pragma unroll
        for (int nt = 0; nt < 8; nt++) {
            const int cb = col0 + wn * 64 + nt * 8 + 2 * t;
            float b0 = 0.f, b1 = 0.f;
            if (MODE == 4) { b0 = bias[cb]; b1 = bias[cb + 1]; }
            float2 v0 = make_float2(acc[mt][nt][0] + b0, acc[mt][nt][1] + b1);
            float2 v1 = make_float2(acc[mt][nt][2] + b0, acc[mt][nt][3] + b1);
            *(float2*)(C + (size_t)ra * N + cb)       = v0;
            *(float2*)(C + (size_t)(ra + 8) * N + cb) = v1;
        }
    }
}

// ---------------------------------------------------------------------------
// Flash attention via tf32 mma (R7, proven — unchanged).
// ---------------------------------------------------------------------------
#define AQ_P 132
#define AK_P 132
#define AV_P 136
#define AP_P 68
#define SM_AQ 0
#define SM_AK (SM_AQ + 128*AQ_P)
#define SM_AV (SM_AK + 64*AK_P)
#define SM_AP (SM_AV + 64*AV_P)
#define ATTN_FLOATS (SM_AP + 128*AP_P)
#define ATTN_SMEM_BYTES (ATTN_FLOATS * 4)  // 171008

__global__ __launch_bounds__(256, 1) void attn_mma()
{
    extern __shared__ float sm[];
    float* Qs = sm + SM_AQ;
    float* Ks = sm + SM_AK;
    float* Vs = sm + SM_AV;
    float* Ps = sm + SM_AP;

    const int tid  = threadIdx.x;
    const int lane = tid & 31;
    const int w    = tid >> 5;
    const int g    = lane >> 2;
    const int t    = lane & 3;
    const int bx   = gridDim.x - 1 - blockIdx.x;
    const int bh   = blockIdx.y;
    const int b    = bh >> 4;
    const int h    = bh & 15;
    const int q0   = bx * 128;
    const int r0   = w * 16;

    const float scale = 0.08838834764831845f;

    {
        int row = tid >> 1;
        int cb  = (tid & 1) * 64;
        const float* src = g_q + (size_t)(b*SEQ + q0 + row) * DM + h*HD + cb;
        float* dst = Qs + row * AQ_P + cb;
#pragma unroll
        for (int i = 0; i < 16; i++) {
            float4 v = *(const float4*)(src + i * 4);
            dst[i*4+0] = f2tf32f(v.x * scale);
            dst[i*4+1] = f2tf32f(v.y * scale);
            dst[i*4+2] = f2tf32f(v.z * scale);
            dst[i*4+3] = f2tf32f(v.w * scale);
        }
    }

    float oacc[16][4];
#pragma unroll
    for (int nt = 0; nt < 16; nt++)
#pragma unroll
        for (int r = 0; r < 4; r++) oacc[nt][r] = 0.f;
    float mA = -1e30f, mB = -1e30f, lA = 0.f, lB = 0.f;

    const int nkt = (q0 + 128) / 64;
    for (int kt = 0; kt < nkt; kt++) {
        const int k0 = kt * 64;
        __syncthreads();

        {
            int row = tid >> 2;
            int cb  = (tid & 3) * 32;
            const float* ksrc = g_k + (size_t)(b*SEQ + k0 + row) * DM + h*HD + cb;
            const float* vsrc = g_v + (size_t)(b*SEQ + k0 + row) * DM + h*HD + cb;
            float* kdst = Ks + row * AK_P + cb;
            float* vdst = Vs + row * AV_P + cb;
#pragma unroll
            for (int i = 0; i < 8; i++) {
                float4 kv = *(const float4*)(ksrc + i * 4);
                kdst[i*4+0] = f2tf32f(kv.x);
                kdst[i*4+1] = f2tf32f(kv.y);
                kdst[i*4+2] = f2tf32f(kv.z);
                kdst[i*4+3] = f2tf32f(kv.w);
                float4 vv = *(const float4*)(vsrc + i * 4);
                vdst[i*4+0] = f2tf32f(vv.x);
                vdst[i*4+1] = f2tf32f(vv.y);
                vdst[i*4+2] = f2tf32f(vv.z);
                vdst[i*4+3] = f2tf32f(vv.w);
            }
        }
        __syncthreads();

        float sacc[8][4];
#pragma unroll
        for (int nt = 0; nt < 8; nt++)
#pragma unroll
            for (int r = 0; r < 4; r++) sacc[nt][r] = 0.f;

#pragma unroll
        for (int s = 0; s < 16; s++) {
            const int kb = s * 8 + t;
            uint32 af[4];
            af[0] = __float_as_uint(Qs[(r0 + g    ) * AQ_P + kb]);
            af[1] = __float_as_uint(Qs[(r0 + 8 + g) * AQ_P + kb]);
            af[2] = __float_as_uint(Qs[(r0 + g    ) * AQ_P + kb + 4]);
            af[3] = __float_as_uint(Qs[(r0 + 8 + g) * AQ_P + kb + 4]);
#pragma unroll
            for (int nt = 0; nt < 8; nt++) {
                uint32 bf[2];
                bf[0] = __float_as_uint(Ks[(nt*8 + g) * AK_P + kb]);
                bf[1] = __float_as_uint(Ks[(nt*8 + g) * AK_P + kb + 4]);
                mma_tf32(sacc[nt], af, bf);
            }
        }

        if (k0 + 63 > q0 + r0) {
            const int rowA = q0 + r0 + g;
            const int rowB = rowA + 8;
#pragma unroll
            for (int nt = 0; nt < 8; nt++) {
                const int col = k0 + nt*8 + 2*t;
                if (col     > rowA) sacc[nt][0] = -1e30f;
                if (col + 1 > rowA) sacc[nt][1] = -1e30f;
                if (col     > rowB) sacc[nt][2] = -1e30f;
                if (col + 1 > rowB) sacc[nt][3] = -1e30f;
            }
        }

        float mxA = -1e30f, mxB = -1e30f;
#pragma unroll
        for (int nt = 0; nt < 8; nt++) {
            mxA = fmaxf(mxA, fmaxf(sacc[nt][0], sacc[nt][1]));
            mxB = fmaxf(mxB, fmaxf(sacc[nt][2], sacc[nt][3]));
        }
        mxA = fmaxf(mxA, __shfl_xor_sync(0xffffffffu, mxA, 1));
        mxA = fmaxf(mxA, __shfl_xor_sync(0xffffffffu, mxA, 2));
        mxB = fmaxf(mxB, __shfl_xor_sync(0xffffffffu, mxB, 1));
        mxB = fmaxf(mxB, __shfl_xor_sync(0xffffffffu, mxB, 2));

        const float mnA = fmaxf(mA, mxA);
        const float mnB = fmaxf(mB, mxB);
        const float corrA = __expf(mA - mnA);
        const float corrB = __expf(mB - mnB);

        float sumA = 0.f, sumB = 0.f;
        __syncwarp();
#pragma unroll
        for (int nt = 0; nt < 8; nt++) {
            float pA0 = __expf(sacc[nt][0] - mnA);
            float pA1 = __expf(sacc[nt][1] - mnA);
            float pB0 = __expf(sacc[nt][2] - mnB);
            float pB1 = __expf(sacc[nt][3] - mnB);
            sumA += pA0 + pA1;
            sumB += pB0 + pB1;
            float2 wa = make_float2(f2tf32f(pA0), f2tf32f(pA1));
            float2 wb = make_float2(f2tf32f(pB0), f2tf32f(pB1));
            *(float2*)(Ps + (r0 + g    ) * AP_P + nt*8 + 2*t) = wa;
            *(float2*)(Ps + (r0 + 8 + g) * AP_P + nt*8 + 2*t) = wb;
        }
        sumA += __shfl_xor_sync(0xffffffffu, sumA, 1);
        sumA += __shfl_xor_sync(0xffffffffu, sumA, 2);
        sumB += __shfl_xor_sync(0xffffffffu, sumB, 1);
        sumB += __shfl_xor_sync(0xffffffffu, sumB, 2);

        lA = lA * corrA + sumA;
        lB = lB * corrB + sumB;
        mA = mnA;
        mB = mnB;

#pragma unroll
        for (int nt = 0; nt < 16; nt++) {
            oacc[nt][0] *= corrA; oacc[nt][1] *= corrA;
            oacc[nt][2] *= corrB; oacc[nt][3] *= corrB;
        }
        __syncwarp();

#pragma unroll
        for (int s = 0; s < 8; s++) {
            const int kb = s * 8 + t;
            uint32 af[4];
            af[0] = __float_as_uint(Ps[(r0 + g    ) * AP_P + kb]);
            af[1] = __float_as_uint(Ps[(r0 + 8 + g) * AP_P + kb]);
            af[2] = __float_as_uint(Ps[(r0 + g    ) * AP_P + kb + 4]);
            af[3] = __float_as_uint(Ps[(r0 + 8 + g) * AP_P + kb + 4]);
#pragma unroll
            for (int nt = 0; nt < 16; nt++) {
                uint32 bf[2];
                bf[0] = __float_as_uint(Vs[(kb    ) * AV_P + nt*8 + g]);
                bf[1] = __float_as_uint(Vs[(kb + 4) * AV_P + nt*8 + g]);
                mma_tf32(oacc[nt], af, bf);
            }
        }
    }

    const float invA = 1.f / lA;
    const float invB = 1.f / lB;
    float* baseA = g_ctx + (size_t)(b*SEQ + q0 + r0 + g    ) * DM + h*HD;
    float* baseB = g_ctx + (size_t)(b*SEQ + q0 + r0 + 8 + g) * DM + h*HD;
#pragma unroll
    for (int nt = 0; nt < 16; nt++) {
        *(float2*)(baseA + nt*8 + 2*t) = make_float2(oacc[nt][0]*invA, oacc[nt][1]*invA);
        *(float2*)(baseB + nt*8 + 2*t) = make_float2(oacc[nt][2]*invB, oacc[nt][3]*invB);
    }
}

// ---------------------------------------------------------------------------
// Launch
// ---------------------------------------------------------------------------
extern "C" void kernel_launch(void* const* d_in, const int* in_sizes, int n_in,
                              void* d_out, int out_size)
{
    (void)in_sizes; (void)n_in; (void)out_size;
    const float* x    = (const float*)d_in[0];
    const float* W_q  = (const float*)d_in[1];
    const float* W_dkv= (const float*)d_in[2];
    const float* W_uk = (const float*)d_in[3];
    const float* W_uv = (const float*)d_in[4];
    const float* W_o  = (const float*)d_in[5];
    const float* W_b  = (const float*)d_in[6];
    float* out = (float*)d_out;

    cudaFuncSetAttribute(attn_mma,
                         cudaFuncAttributeMaxDynamicSharedMemorySize,
                         ATTN_SMEM_BYTES);

    dim3 blk(256);
    tgemm_nt<0><<<dim3(DL/128, TOK/128), blk>>>(x, W_dkv, nullptr, nullptr, TOK, DL, DM);
    tgemm_nt<1><<<dim3(DM/128, TOK/128), blk>>>(x, W_q, nullptr, nullptr, TOK, DM, DM);
    tgemm_nt<2><<<dim3(DM/128, TOK/128), blk>>>(nullptr, W_uk, nullptr, nullptr, TOK, DM, DL);
    tgemm_nt<3><<<dim3(DM/128, TOK/128), blk>>>(nullptr, W_uv, nullptr, nullptr, TOK, DM, DL);
    attn_mma<<<dim3(SEQ/128, NB*NH), dim3(256), ATTN_SMEM_BYTES>>>();
    tgemm_nt<4><<<dim3(DM/128, TOK/128), blk>>>(nullptr, W_o, W_b, out, TOK, DM, DM);
}

// round 13
// speedup vs baseline: 1.0591x; 1.0517x over previous
#include <cuda_runtime.h>

#define DM   2048     // d_model
#define DL   512      // d_latent
#define NH   16
#define HD   128
#define SEQ  2048
#define NB   2
#define TOK  (NB*SEQ) // 4096

typedef unsigned int uint32;

// ---- tf32 mma helpers (layout verified in R6) ----
__device__ __forceinline__ uint32 f2tf32(float f) {
    uint32 u;
    asm("cvt.rna.tf32.f32 %0, %1;" : "=r"(u) : "f"(f));
    return u;
}
__device__ __forceinline__ void mma_tf32(float* d, const uint32* a, const uint32* b) {
    asm volatile(
        "mma.sync.aligned.m16n8k8.row.col.f32.tf32.tf32.f32 "
        "{%0,%1,%2,%3}, {%4,%5,%6,%7}, {%8,%9}, {%0,%1,%2,%3};"
        : "+f"(d[0]), "+f"(d[1]), "+f"(d[2]), "+f"(d[3])
        : "r"(a[0]), "r"(a[1]), "r"(a[2]), "r"(a[3]), "r"(b[0]), "r"(b[1]));
}

// Scratch (allocation-free rule: __device__ globals, device-code refs only)
__device__ float g_q  [TOK*DM];
__device__ float g_ckv[TOK*DL];
__device__ float g_k  [TOK*DM];
__device__ float g_v  [TOK*DM];
__device__ float g_ctx[TOK*DM];

// ---------------------------------------------------------------------------
// C[M,N] = A[M,K] @ B[N,K]^T  (+ optional bias[N]) via tf32 mma.
// R7-proven structure: BK=32, 256 threads, single-buffer static smem, GP=36.
// MTILES: 2 -> 128-row block (warp tile 32x64), 1 -> 64-row block (warp 16x64,
// used for the small ckv GEMM to double its grid to a full wave).
// MODE: 0=ckv  1=q  23=k+v fused (blockIdx.x selects W_uk/g_k vs W_uv/g_v,
// second B passed via 'bias' arg)  4=out(+bias).
// ---------------------------------------------------------------------------
#define GP 36   // smem pitch (floats)

template<int MODE, int MTILES>
__global__ __launch_bounds__(256) void tgemm_nt(
    const float* __restrict__ Aarg, const float* __restrict__ B,
    const float* __restrict__ bias, float* __restrict__ Carg,
    int M, int N, int K)
{
    const float* A;
    const float* Bp;
    float* C;
    int bx = blockIdx.x;
    if      (MODE == 0)  { A = Aarg;  C = g_ckv; Bp = B; }
    else if (MODE == 1)  { A = Aarg;  C = g_q;   Bp = B; }
    else if (MODE == 23) {
        A = g_ckv;
        const bool isV = bx >= (DM / 128);
        bx &= (DM / 128) - 1;
        C  = isV ? g_v : g_k;
        Bp = isV ? bias : B;   // bias arg carries W_uv in this mode
    }
    else                 { A = g_ctx; C = Carg;  Bp = B; }

    constexpr int MROWS = 64 * MTILES;          // A-tile rows per block
    __shared__ float As[MROWS][GP];
    __shared__ float Bs[128][GP];

    const int tid  = threadIdx.x;
    const int lane = tid & 31;
    const int w    = tid >> 5;
    const int g    = lane >> 2;
    const int t    = lane & 3;
    const int wm   = w & 3;                      // 4 M-slots of 16*MTILES rows
    const int wn   = w >> 2;                     // 2 N-slots of 64 cols
    const int row0 = blockIdx.y * MROWS;
    const int col0 = bx * 128;

    // A loader: 256/MROWS threads per row, 32/(256/MROWS) k each
    constexpr int TPR_A = 256 / MROWS;           // 2 (MT=2) or 4 (MT=1)
    constexpr int KPT_A = 32 / TPR_A;            // 16 or 8
    constexpr int NV_A  = KPT_A / 4;             // float4s: 4 or 2
    const int alr  = tid / TPR_A;
    const int alko = (tid % TPR_A) * KPT_A;
    // B loader: 2 threads per row, 16 k each (unchanged)
    const int blr  = tid >> 1;
    const int blko = (tid & 1) * 16;

    float acc[MTILES][8][4];
#pragma unroll
    for (int mt = 0; mt < MTILES; mt++)
#pragma unroll
        for (int nt = 0; nt < 8; nt++)
#pragma unroll
            for (int r = 0; r < 4; r++) acc[mt][nt][r] = 0.f;

    float4 pa[NV_A], pb[4];
#pragma unroll
    for (int i = 0; i < NV_A; i++)
        pa[i] = *(const float4*)(A + (size_t)(row0 + alr) * K + alko + i * 4);
#pragma unroll
    for (int i = 0; i < 4; i++)
        pb[i] = *(const float4*)(Bp + (size_t)(col0 + blr) * K + blko + i * 4);

    for (int k0 = 0; k0 < K; k0 += 32) {
        __syncthreads();
#pragma unroll
        for (int i = 0; i < NV_A; i++) {
            float4 va = pa[i];
            float4 ca;
            ca.x = __uint_as_float(f2tf32(va.x)); ca.y = __uint_as_float(f2tf32(va.y));
            ca.z = __uint_as_float(f2tf32(va.z)); ca.w = __uint_as_float(f2tf32(va.w));
            *(float4*)&As[alr][alko + i * 4] = ca;
        }
#pragma unroll
        for (int i = 0; i < 4; i++) {
            float4 vb = pb[i];
            float4 cb;
            cb.x = __uint_as_float(f2tf32(vb.x)); cb.y = __uint_as_float(f2tf32(vb.y));
            cb.z = __uint_as_float(f2tf32(vb.z)); cb.w = __uint_as_float(f2tf32(vb.w));
            *(float4*)&Bs[blr][blko + i * 4] = cb;
        }
        __syncthreads();

        if (k0 + 32 < K) {
#pragma unroll
            for (int i = 0; i < NV_A; i++)
                pa[i] = *(const float4*)(A + (size_t)(row0 + alr) * K + k0 + 32 + alko + i * 4);
#pragma unroll
            for (int i = 0; i < 4; i++)
                pb[i] = *(const float4*)(Bp + (size_t)(col0 + blr) * K + k0 + 32 + blko + i * 4);
        }

#pragma unroll
        for (int s = 0; s < 4; s++) {
            const int kb = s * 8 + t;
            uint32 af[MTILES][4], bf[8][2];
#pragma unroll
            for (int mt = 0; mt < MTILES; mt++) {
                const int rb = wm * (16 * MTILES) + mt * 16;
                af[mt][0] = __float_as_uint(As[rb + g    ][kb]);
                af[mt][1] = __float_as_uint(As[rb + 8 + g][kb]);
                af[mt][2] = __float_as_uint(As[rb + g    ][kb + 4]);
                af[mt][3] = __float_as_uint(As[rb + 8 + g][kb + 4]);
            }
#pragma unroll
            for (int nt = 0; nt < 8; nt++) {
                const int nb = wn * 64 + nt * 8 + g;
                bf[nt][0] = __float_as_uint(Bs[nb][kb]);
                bf[nt][1] = __float_as_uint(Bs[nb][kb + 4]);
            }
#pragma unroll
            for (int mt = 0; mt < MTILES; mt++)
#pragma unroll
                for (int nt = 0; nt < 8; nt++)
                    mma_tf32(acc[mt][nt], af[mt], bf[nt]);
        }
    }

#pragma unroll
    for (int mt = 0; mt < MTILES; mt++) {
        const int ra = row0 + wm * (16 * MTILES) + mt * 16 + g;
#pragma unroll
        for (int nt = 0; nt < 8; nt++) {
            const int cb = col0 + wn * 64 + nt * 8 + 2 * t;
            float b0 = 0.f, b1 = 0.f;
            if (MODE == 4) { b0 = bias[cb]; b1 = bias[cb + 1]; }
            float2 v0 = make_float2(acc[mt][nt][0] + b0, acc[mt][nt][1] + b1);
            float2 v1 = make_float2(acc[mt][nt][2] + b0, acc[mt][nt][3] + b1);
            *(float2*)(C + (size_t)ra * N + cb)       = v0;
            *(float2*)(C + (size_t)(ra + 8) * N + cb) = v1;
        }
    }
}

// ---------------------------------------------------------------------------
// Flash attention via tf32 mma (R7, proven — unchanged).
// ---------------------------------------------------------------------------
#define AQ_P 132
#define AK_P 132
#define AV_P 136
#define AP_P 68
#define SM_AQ 0
#define SM_AK (SM_AQ + 128*AQ_P)
#define SM_AV (SM_AK + 64*AK_P)
#define SM_AP (SM_AV + 64*AV_P)
#define ATTN_FLOATS (SM_AP + 128*AP_P)
#define ATTN_SMEM_BYTES (ATTN_FLOATS * 4)  // 171008

__global__ __launch_bounds__(256, 1) void attn_mma()
{
    extern __shared__ float sm[];
    float* Qs = sm + SM_AQ;
    float* Ks = sm + SM_AK;
    float* Vs = sm + SM_AV;
    float* Ps = sm + SM_AP;

    const int tid  = threadIdx.x;
    const int lane = tid & 31;
    const int w    = tid >> 5;
    const int g    = lane >> 2;
    const int t    = lane & 3;
    const int bx   = gridDim.x - 1 - blockIdx.x;
    const int bh   = blockIdx.y;
    const int b    = bh >> 4;
    const int h    = bh & 15;
    const int q0   = bx * 128;
    const int r0   = w * 16;

    const float scale = 0.08838834764831845f;

    {
        int row = tid >> 1;
        int cb  = (tid & 1) * 64;
        const float* src = g_q + (size_t)(b*SEQ + q0 + row) * DM + h*HD + cb;
        float* dst = Qs + row * AQ_P + cb;
#pragma unroll
        for (int i = 0; i < 16; i++) {
            float4 v = *(const float4*)(src + i * 4);
            dst[i*4+0] = __uint_as_float(f2tf32(v.x * scale));
            dst[i*4+1] = __uint_as_float(f2tf32(v.y * scale));
            dst[i*4+2] = __uint_as_float(f2tf32(v.z * scale));
            dst[i*4+3] = __uint_as_float(f2tf32(v.w * scale));
        }
    }

    float oacc[16][4];
#pragma unroll
    for (int nt = 0; nt < 16; nt++)
#pragma unroll
        for (int r = 0; r < 4; r++) oacc[nt][r] = 0.f;
    float mA = -1e30f, mB = -1e30f, lA = 0.f, lB = 0.f;

    const int nkt = (q0 + 128) / 64;
    for (int kt = 0; kt < nkt; kt++) {
        const int k0 = kt * 64;
        __syncthreads();

        {
            int row = tid >> 2;
            int cb  = (tid & 3) * 32;
            const float* ksrc = g_k + (size_t)(b*SEQ + k0 + row) * DM + h*HD + cb;
            const float* vsrc = g_v + (size_t)(b*SEQ + k0 + row) * DM + h*HD + cb;
            float* kdst = Ks + row * AK_P + cb;
            float* vdst = Vs + row * AV_P + cb;
#pragma unroll
            for (int i = 0; i < 8; i++) {
                float4 kv = *(const float4*)(ksrc + i * 4);
                kdst[i*4+0] = __uint_as_float(f2tf32(kv.x));
                kdst[i*4+1] = __uint_as_float(f2tf32(kv.y));
                kdst[i*4+2] = __uint_as_float(f2tf32(kv.z));
                kdst[i*4+3] = __uint_as_float(f2tf32(kv.w));
                float4 vv = *(const float4*)(vsrc + i * 4);
                vdst[i*4+0] = __uint_as_float(f2tf32(vv.x));
                vdst[i*4+1] = __uint_as_float(f2tf32(vv.y));
                vdst[i*4+2] = __uint_as_float(f2tf32(vv.z));
                vdst[i*4+3] = __uint_as_float(f2tf32(vv.w));
            }
        }
        __syncthreads();

        float sacc[8][4];
#pragma unroll
        for (int nt = 0; nt < 8; nt++)
#pragma unroll
            for (int r = 0; r < 4; r++) sacc[nt][r] = 0.f;

#pragma unroll
        for (int s = 0; s < 16; s++) {
            const int kb = s * 8 + t;
            uint32 af[4];
            af[0] = __float_as_uint(Qs[(r0 + g    ) * AQ_P + kb]);
            af[1] = __float_as_uint(Qs[(r0 + 8 + g) * AQ_P + kb]);
            af[2] = __float_as_uint(Qs[(r0 + g    ) * AQ_P + kb + 4]);
            af[3] = __float_as_uint(Qs[(r0 + 8 + g) * AQ_P + kb + 4]);
#pragma unroll
            for (int nt = 0; nt < 8; nt++) {
                uint32 bf[2];
                bf[0] = __float_as_uint(Ks[(nt*8 + g) * AK_P + kb]);
                bf[1] = __float_as_uint(Ks[(nt*8 + g) * AK_P + kb + 4]);
                mma_tf32(sacc[nt], af, bf);
            }
        }

        if (k0 + 63 > q0 + r0) {
            const int rowA = q0 + r0 + g;
            const int rowB = rowA + 8;
#pragma unroll
            for (int nt = 0; nt < 8; nt++) {
                const int col = k0 + nt*8 + 2*t;
                if (col     > rowA) sacc[nt][0] = -1e30f;
                if (col + 1 > rowA) sacc[nt][1] = -1e30f;
                if (col     > rowB) sacc[nt][2] = -1e30f;
                if (col + 1 > rowB) sacc[nt][3] = -1e30f;
            }
        }

        float mxA = -1e30f, mxB = -1e30f;
#pragma unroll
        for (int nt = 0; nt < 8; nt++) {
            mxA = fmaxf(mxA, fmaxf(sacc[nt][0], sacc[nt][1]));
            mxB = fmaxf(mxB, fmaxf(sacc[nt][2], sacc[nt][3]));
        }
        mxA = fmaxf(mxA, __shfl_xor_sync(0xffffffffu, mxA, 1));
        mxA = fmaxf(mxA, __shfl_xor_sync(0xffffffffu, mxA, 2));
        mxB = fmaxf(mxB, __shfl_xor_sync(0xffffffffu, mxB, 1));
        mxB = fmaxf(mxB, __shfl_xor_sync(0xffffffffu, mxB, 2));

        const float mnA = fmaxf(mA, mxA);
        const float mnB = fmaxf(mB, mxB);
        const float corrA = __expf(mA - mnA);
        const float corrB = __expf(mB - mnB);

        float sumA = 0.f, sumB = 0.f;
        __syncwarp();
#pragma unroll
        for (int nt = 0; nt < 8; nt++) {
            float pA0 = __expf(sacc[nt][0] - mnA);
            float pA1 = __expf(sacc[nt][1] - mnA);
            float pB0 = __expf(sacc[nt][2] - mnB);
            float pB1 = __expf(sacc[nt][3] - mnB);
            sumA += pA0 + pA1;
            sumB += pB0 + pB1;
            float2 wa = make_float2(__uint_as_float(f2tf32(pA0)),
                                    __uint_as_float(f2tf32(pA1)));
            float2 wb = make_float2(__uint_as_float(f2tf32(pB0)),
                                    __uint_as_float(f2tf32(pB1)));
            *(float2*)(Ps + (r0 + g    ) * AP_P + nt*8 + 2*t) = wa;
            *(float2*)(Ps + (r0 + 8 + g) * AP_P + nt*8 + 2*t) = wb;
        }
        sumA += __shfl_xor_sync(0xffffffffu, sumA, 1);
        sumA += __shfl_xor_sync(0xffffffffu, sumA, 2);
        sumB += __shfl_xor_sync(0xffffffffu, sumB, 1);
        sumB += __shfl_xor_sync(0xffffffffu, sumB, 2);

        lA = lA * corrA + sumA;
        lB = lB * corrB + sumB;
        mA = mnA;
        mB = mnB;

#pragma unroll
        for (int nt = 0; nt < 16; nt++) {
            oacc[nt][0] *= corrA; oacc[nt][1] *= corrA;
            oacc[nt][2] *= corrB; oacc[nt][3] *= corrB;
        }
        __syncwarp();

#pragma unroll
        for (int s = 0; s < 8; s++) {
            const int kb = s * 8 + t;
            uint32 af[4];
            af[0] = __float_as_uint(Ps[(r0 + g    ) * AP_P + kb]);
            af[1] = __float_as_uint(Ps[(r0 + 8 + g) * AP_P + kb]);
            af[2] = __float_as_uint(Ps[(r0 + g    ) * AP_P + kb + 4]);
            af[3] = __float_as_uint(Ps[(r0 + 8 + g) * AP_P + kb + 4]);
#pragma unroll
            for (int nt = 0; nt < 16; nt++) {
                uint32 bf[2];
                bf[0] = __float_as_uint(Vs[(kb    ) * AV_P + nt*8 + g]);
                bf[1] = __float_as_uint(Vs[(kb + 4) * AV_P + nt*8 + g]);
                mma_tf32(oacc[nt], af, bf);
            }
        }
    }

    const float invA = 1.f / lA;
    const float invB = 1.f / lB;
    float* baseA = g_ctx + (size_t)(b*SEQ + q0 + r0 + g    ) * DM + h*HD;
    float* baseB = g_ctx + (size_t)(b*SEQ + q0 + r0 + 8 + g) * DM + h*HD;
#pragma unroll
    for (int nt = 0; nt < 16; nt++) {
        *(float2*)(baseA + nt*8 + 2*t) = make_float2(oacc[nt][0]*invA, oacc[nt][1]*invA);
        *(float2*)(baseB + nt*8 + 2*t) = make_float2(oacc[nt][2]*invB, oacc[nt][3]*invB);
    }
}

// ---------------------------------------------------------------------------
// Launch: strictly serial, stateless, static smem GEMMs.
// ---------------------------------------------------------------------------
extern "C" void kernel_launch(void* const* d_in, const int* in_sizes, int n_in,
                              void* d_out, int out_size)
{
    (void)in_sizes; (void)n_in; (void)out_size;
    const float* x    = (const float*)d_in[0];
    const float* W_q  = (const float*)d_in[1];
    const float* W_dkv= (const float*)d_in[2];
    const float* W_uk = (const float*)d_in[3];
    const float* W_uv = (const float*)d_in[4];
    const float* W_o  = (const float*)d_in[5];
    const float* W_b  = (const float*)d_in[6];
    float* out = (float*)d_out;

    cudaFuncSetAttribute(attn_mma,
                         cudaFuncAttributeMaxDynamicSharedMemorySize,
                         ATTN_SMEM_BYTES);

    dim3 blk(256);
    // ckv = x @ W_dkv^T : 64-row tiles -> 256 blocks (full wave)
    tgemm_nt<0, 1><<<dim3(DL/128, TOK/64), blk>>>(x, W_dkv, nullptr, nullptr, TOK, DL, DM);
    // q = x @ W_q^T
    tgemm_nt<1, 2><<<dim3(DM/128, TOK/128), blk>>>(x, W_q, nullptr, nullptr, TOK, DM, DM);
    // k,v = ckv @ {W_uk,W_uv}^T fused in one launch (W_uv via bias arg)
    tgemm_nt<23, 2><<<dim3(2*DM/128, TOK/128), blk>>>(nullptr, W_uk, W_uv, nullptr, TOK, DM, DL);
    // attention
    attn_mma<<<dim3(SEQ/128, NB*NH), dim3(256), ATTN_SMEM_BYTES>>>();
    // out = ctx @ W_o^T + b
    tgemm_nt<4, 2><<<dim3(DM/128, TOK/128), blk>>>(nullptr, W_o, W_b, out, TOK, DM, DM);
}

// round 16
// speedup vs baseline: 1.0759x; 1.0159x over previous
#include <cuda_runtime.h>

#define DM   2048     // d_model
#define DL   512      // d_latent
#define NH   16
#define HD   128
#define SEQ  2048
#define NB   2
#define TOK  (NB*SEQ) // 4096

typedef unsigned int uint32;

// ---- tf32 mma helpers (layout verified in R6) ----
__device__ __forceinline__ uint32 f2tf32(float f) {
    uint32 u;
    asm("cvt.rna.tf32.f32 %0, %1;" : "=r"(u) : "f"(f));
    return u;
}
__device__ __forceinline__ void mma_tf32(float* d, const uint32* a, const uint32* b) {
    asm volatile(
        "mma.sync.aligned.m16n8k8.row.col.f32.tf32.tf32.f32 "
        "{%0,%1,%2,%3}, {%4,%5,%6,%7}, {%8,%9}, {%0,%1,%2,%3};"
        : "+f"(d[0]), "+f"(d[1]), "+f"(d[2]), "+f"(d[3])
        : "r"(a[0]), "r"(a[1]), "r"(a[2]), "r"(a[3]), "r"(b[0]), "r"(b[1]));
}

// Scratch (allocation-free rule: __device__ globals, device-code refs only)
__device__ float g_q  [TOK*DM];
__device__ float g_ckv[TOK*DL];
__device__ float g_k  [TOK*DM];
__device__ float g_v  [TOK*DM];
__device__ float g_ctx[TOK*DM];

// ---------------------------------------------------------------------------
// C[M,N] = A[M,K] @ B[N,K]^T  (+ optional bias[N]) via tf32 mma.
// EXACT R13 GEMM (proven): BK=32, 256 threads, single-buffer static smem,
// GP=36, scalar LDS.32 fragment loads.
// MTILES: 2 -> 128-row block, 1 -> 64-row block (ckv full-wave grid).
// MODE: 0=ckv  1=q  23=k+v fused  4=out(+bias).
// ---------------------------------------------------------------------------
#define GP 36   // smem pitch (floats)

template<int MODE, int MTILES>
__global__ __launch_bounds__(256) void tgemm_nt(
    const float* __restrict__ Aarg, const float* __restrict__ B,
    const float* __restrict__ bias, float* __restrict__ Carg,
    int M, int N, int K)
{
    const float* A;
    const float* Bp;
    float* C;
    int bx = blockIdx.x;
    if      (MODE == 0)  { A = Aarg;  C = g_ckv; Bp = B; }
    else if (MODE == 1)  { A = Aarg;  C = g_q;   Bp = B; }
    else if (MODE == 23) {
        A = g_ckv;
        const bool isV = bx >= (DM / 128);
        bx &= (DM / 128) - 1;
        C  = isV ? g_v : g_k;
        Bp = isV ? bias : B;   // bias arg carries W_uv in this mode
    }
    else                 { A = g_ctx; C = Carg;  Bp = B; }

    constexpr int MROWS = 64 * MTILES;
    __shared__ float As[MROWS][GP];
    __shared__ float Bs[128][GP];

    const int tid  = threadIdx.x;
    const int lane = tid & 31;
    const int w    = tid >> 5;
    const int g    = lane >> 2;
    const int t    = lane & 3;
    const int wm   = w & 3;
    const int wn   = w >> 2;
    const int row0 = blockIdx.y * MROWS;
    const int col0 = bx * 128;

    constexpr int TPR_A = 256 / MROWS;
    constexpr int KPT_A = 32 / TPR_A;
    constexpr int NV_A  = KPT_A / 4;
    const int alr  = tid / TPR_A;
    const int alko = (tid % TPR_A) * KPT_A;
    const int blr  = tid >> 1;
    const int blko = (tid & 1) * 16;

    float acc[MTILES][8][4];
#pragma unroll
    for (int mt = 0; mt < MTILES; mt++)
#pragma unroll
        for (int nt = 0; nt < 8; nt++)
#pragma unroll
            for (int r = 0; r < 4; r++) acc[mt][nt][r] = 0.f;

    float4 pa[NV_A], pb[4];
#pragma unroll
    for (int i = 0; i < NV_A; i++)
        pa[i] = *(const float4*)(A + (size_t)(row0 + alr) * K + alko + i * 4);
#pragma unroll
    for (int i = 0; i < 4; i++)
        pb[i] = *(const float4*)(Bp + (size_t)(col0 + blr) * K + blko + i * 4);

    for (int k0 = 0; k0 < K; k0 += 32) {
        __syncthreads();
#pragma unroll
        for (int i = 0; i < NV_A; i++) {
            float4 va = pa[i];
            float4 ca;
            ca.x = __uint_as_float(f2tf32(va.x)); ca.y = __uint_as_float(f2tf32(va.y));
            ca.z = __uint_as_float(f2tf32(va.z)); ca.w = __uint_as_float(f2tf32(va.w));
            *(float4*)&As[alr][alko + i * 4] = ca;
        }
#pragma unroll
        for (int i = 0; i < 4; i++) {
            float4 vb = pb[i];
            float4 cb;
            cb.x = __uint_as_float(f2tf32(vb.x)); cb.y = __uint_as_float(f2tf32(vb.y));
            cb.z = __uint_as_float(f2tf32(vb.z)); cb.w = __uint_as_float(f2tf32(vb.w));
            *(float4*)&Bs[blr][blko + i * 4] = cb;
        }
        __syncthreads();

        if (k0 + 32 < K) {
#pragma unroll
            for (int i = 0; i < NV_A; i++)
                pa[i] = *(const float4*)(A + (size_t)(row0 + alr) * K + k0 + 32 + alko + i * 4);
#pragma unroll
            for (int i = 0; i < 4; i++)
                pb[i] = *(const float4*)(Bp + (size_t)(col0 + blr) * K + k0 + 32 + blko + i * 4);
        }

#pragma unroll
        for (int s = 0; s < 4; s++) {
            const int kb = s * 8 + t;
            uint32 af[MTILES][4], bf[8][2];
#pragma unroll
            for (int mt = 0; mt < MTILES; mt++) {
                const int rb = wm * (16 * MTILES) + mt * 16;
                af[mt][0] = __float_as_uint(As[rb + g    ][kb]);
                af[mt][1] = __float_as_uint(As[rb + 8 + g][kb]);
                af[mt][2] = __float_as_uint(As[rb + g    ][kb + 4]);
                af[mt][3] = __float_as_uint(As[rb + 8 + g][kb + 4]);
            }
#pragma unroll
            for (int nt = 0; nt < 8; nt++) {
                const int nb = wn * 64 + nt * 8 + g;
                bf[nt][0] = __float_as_uint(Bs[nb][kb]);
                bf[nt][1] = __float_as_uint(Bs[nb][kb + 4]);
            }
#pragma unroll
            for (int mt = 0; mt < MTILES; mt++)
#pragma unroll
                for (int nt = 0; nt < 8; nt++)
                    mma_tf32(acc[mt][nt], af[mt], bf[nt]);
        }
    }

#pragma unroll
    for (int mt = 0; mt < MTILES; mt++) {
        const int ra = row0 + wm * (16 * MTILES) + mt * 16 + g;
#pragma unroll
        for (int nt = 0; nt < 8; nt++) {
            const int cb = col0 + wn * 64 + nt * 8 + 2 * t;
            float b0 = 0.f, b1 = 0.f;
            if (MODE == 4) { b0 = bias[cb]; b1 = bias[cb + 1]; }
            float2 v0 = make_float2(acc[mt][nt][0] + b0, acc[mt][nt][1] + b1);
            float2 v1 = make_float2(acc[mt][nt][2] + b0, acc[mt][nt][3] + b1);
            *(float2*)(C + (size_t)ra * N + cb)       = v0;
            *(float2*)(C + (size_t)(ra + 8) * N + cb) = v1;
        }
    }
}

// ---------------------------------------------------------------------------
// Flash attention via tf32 mma (R13 compute, scalar LDS fragments) +
//   (a) K/V register prefetch: next tile's 16 LDG.128 issued under compute
//       (GEMM-proven pipeline; occupancy is smem-bound so +64 regs is free)
//   (b) masked-tile skip: exact no-op tiles skipped per-warp (barrier counts
//       stay uniform; a fully-masked tile contributes corr=1, sum=0)
// ---------------------------------------------------------------------------
#define AQ_P 132
#define AK_P 132
#define AV_P 136
#define AP_P 68
#define SM_AQ 0
#define SM_AK (SM_AQ + 128*AQ_P)
#define SM_AV (SM_AK + 64*AK_P)
#define SM_AP (SM_AV + 64*AV_P)
#define ATTN_FLOATS (SM_AP + 128*AP_P)
#define ATTN_SMEM_BYTES (ATTN_FLOATS * 4)  // 171008

__global__ __launch_bounds__(256, 1) void attn_mma()
{
    extern __shared__ float sm[];
    float* Qs = sm + SM_AQ;
    float* Ks = sm + SM_AK;
    float* Vs = sm + SM_AV;
    float* Ps = sm + SM_AP;

    const int tid  = threadIdx.x;
    const int lane = tid & 31;
    const int w    = tid >> 5;
    const int g    = lane >> 2;
    const int t    = lane & 3;
    const int bx   = gridDim.x - 1 - blockIdx.x;
    const int bh   = blockIdx.y;
    const int b    = bh >> 4;
    const int h    = bh & 15;
    const int q0   = bx * 128;
    const int r0   = w * 16;

    const float scale = 0.08838834764831845f;

    // K/V loader mapping
    const int krow = tid >> 2;
    const int kcb  = (tid & 3) * 32;
    const float* kbase = g_k + (size_t)(b*SEQ + krow) * DM + h*HD + kcb;
    const float* vbase = g_v + (size_t)(b*SEQ + krow) * DM + h*HD + kcb;

    // ---- load Q (scaled + tf32) ----
    {
        int row = tid >> 1;
        int cb  = (tid & 1) * 64;
        const float* src = g_q + (size_t)(b*SEQ + q0 + row) * DM + h*HD + cb;
        float* dst = Qs + row * AQ_P + cb;
#pragma unroll
        for (int i = 0; i < 16; i++) {
            float4 v = *(const float4*)(src + i * 4);
            dst[i*4+0] = __uint_as_float(f2tf32(v.x * scale));
            dst[i*4+1] = __uint_as_float(f2tf32(v.y * scale));
            dst[i*4+2] = __uint_as_float(f2tf32(v.z * scale));
            dst[i*4+3] = __uint_as_float(f2tf32(v.w * scale));
        }
    }

    float oacc[16][4];
#pragma unroll
    for (int nt = 0; nt < 16; nt++)
#pragma unroll
        for (int r = 0; r < 4; r++) oacc[nt][r] = 0.f;
    float mA = -1e30f, mB = -1e30f, lA = 0.f, lB = 0.f;

    const int nkt = (q0 + 128) / 64;

    // ---- prefetch tile 0 K/V into registers ----
    float4 pk[8], pv[8];
#pragma unroll
    for (int i = 0; i < 8; i++) {
        pk[i] = *(const float4*)(kbase + i * 4);
        pv[i] = *(const float4*)(vbase + i * 4);
    }

    for (int kt = 0; kt < nkt; kt++) {
        const int k0 = kt * 64;
        __syncthreads();   // all warps done with prior Ks/Vs (and Q stores, iter 0)

        // ---- convert + store prefetched K/V tile ----
        {
            float* kdst = Ks + krow * AK_P + kcb;
            float* vdst = Vs + krow * AV_P + kcb;
#pragma unroll
            for (int i = 0; i < 8; i++) {
                float4 kv = pk[i];
                kdst[i*4+0] = __uint_as_float(f2tf32(kv.x));
                kdst[i*4+1] = __uint_as_float(f2tf32(kv.y));
                kdst[i*4+2] = __uint_as_float(f2tf32(kv.z));
                kdst[i*4+3] = __uint_as_float(f2tf32(kv.w));
                float4 vv = pv[i];
                vdst[i*4+0] = __uint_as_float(f2tf32(vv.x));
                vdst[i*4+1] = __uint_as_float(f2tf32(vv.y));
                vdst[i*4+2] = __uint_as_float(f2tf32(vv.z));
                vdst[i*4+3] = __uint_as_float(f2tf32(vv.w));
            }
        }
        __syncthreads();

        // ---- issue next tile's loads (hidden under compute below) ----
        if (kt + 1 < nkt) {
            const size_t off = (size_t)(k0 + 64) * DM;
#pragma unroll
            for (int i = 0; i < 8; i++) {
                pk[i] = *(const float4*)(kbase + off + i * 4);
                pv[i] = *(const float4*)(vbase + off + i * 4);
            }
        }

        // Tile entirely above this warp's diagonal -> exact no-op, skip compute.
        if (k0 > q0 + r0 + 15) continue;

        // ---- S = Q @ K^T ----
        float sacc[8][4];
#pragma unroll
        for (int nt = 0; nt < 8; nt++)
#pragma unroll
            for (int r = 0; r < 4; r++) sacc[nt][r] = 0.f;

#pragma unroll
        for (int s = 0; s < 16; s++) {
            const int kb = s * 8 + t;
            uint32 af[4];
            af[0] = __float_as_uint(Qs[(r0 + g    ) * AQ_P + kb]);
            af[1] = __float_as_uint(Qs[(r0 + 8 + g) * AQ_P + kb]);
            af[2] = __float_as_uint(Qs[(r0 + g    ) * AQ_P + kb + 4]);
            af[3] = __float_as_uint(Qs[(r0 + 8 + g) * AQ_P + kb + 4]);
#pragma unroll
            for (int nt = 0; nt < 8; nt++) {
                uint32 bf[2];
                bf[0] = __float_as_uint(Ks[(nt*8 + g) * AK_P + kb]);
                bf[1] = __float_as_uint(Ks[(nt*8 + g) * AK_P + kb + 4]);
                mma_tf32(sacc[nt], af, bf);
            }
        }

        if (k0 + 63 > q0 + r0) {
            const int rowA = q0 + r0 + g;
            const int rowB = rowA + 8;
#pragma unroll
            for (int nt = 0; nt < 8; nt++) {
                const int col = k0 + nt*8 + 2*t;
                if (col     > rowA) sacc[nt][0] = -1e30f;
                if (col + 1 > rowA) sacc[nt][1] = -1e30f;
                if (col     > rowB) sacc[nt][2] = -1e30f;
                if (col + 1 > rowB) sacc[nt][3] = -1e30f;
            }
        }

        // ---- online softmax (quad reduction) ----
        float mxA = -1e30f, mxB = -1e30f;
#pragma unroll
        for (int nt = 0; nt < 8; nt++) {
            mxA = fmaxf(mxA, fmaxf(sacc[nt][0], sacc[nt][1]));
            mxB = fmaxf(mxB, fmaxf(sacc[nt][2], sacc[nt][3]));
        }
        mxA = fmaxf(mxA, __shfl_xor_sync(0xffffffffu, mxA, 1));
        mxA = fmaxf(mxA, __shfl_xor_sync(0xffffffffu, mxA, 2));
        mxB = fmaxf(mxB, __shfl_xor_sync(0xffffffffu, mxB, 1));
        mxB = fmaxf(mxB, __shfl_xor_sync(0xffffffffu, mxB, 2));

        const float mnA = fmaxf(mA, mxA);
        const float mnB = fmaxf(mB, mxB);
        const float corrA = __expf(mA - mnA);
        const float corrB = __expf(mB - mnB);

        float sumA = 0.f, sumB = 0.f;
        __syncwarp();
#pragma unroll
        for (int nt = 0; nt < 8; nt++) {
            float pA0 = __expf(sacc[nt][0] - mnA);
            float pA1 = __expf(sacc[nt][1] - mnA);
            float pB0 = __expf(sacc[nt][2] - mnB);
            float pB1 = __expf(sacc[nt][3] - mnB);
            sumA += pA0 + pA1;
            sumB += pB0 + pB1;
            float2 wa = make_float2(__uint_as_float(f2tf32(pA0)),
                                    __uint_as_float(f2tf32(pA1)));
            float2 wb = make_float2(__uint_as_float(f2tf32(pB0)),
                                    __uint_as_float(f2tf32(pB1)));
            *(float2*)(Ps + (r0 + g    ) * AP_P + nt*8 + 2*t) = wa;
            *(float2*)(Ps + (r0 + 8 + g) * AP_P + nt*8 + 2*t) = wb;
        }
        sumA += __shfl_xor_sync(0xffffffffu, sumA, 1);
        sumA += __shfl_xor_sync(0xffffffffu, sumA, 2);
        sumB += __shfl_xor_sync(0xffffffffu, sumB, 1);
        sumB += __shfl_xor_sync(0xffffffffu, sumB, 2);

        lA = lA * corrA + sumA;
        lB = lB * corrB + sumB;
        mA = mnA;
        mB = mnB;

#pragma unroll
        for (int nt = 0; nt < 16; nt++) {
            oacc[nt][0] *= corrA; oacc[nt][1] *= corrA;
            oacc[nt][2] *= corrB; oacc[nt][3] *= corrB;
        }
        __syncwarp();

        // ---- O += P @ V ----
#pragma unroll
        for (int s = 0; s < 8; s++) {
            const int kb = s * 8 + t;
            uint32 af[4];
            af[0] = __float_as_uint(Ps[(r0 + g    ) * AP_P + kb]);
            af[1] = __float_as_uint(Ps[(r0 + 8 + g) * AP_P + kb]);
            af[2] = __float_as_uint(Ps[(r0 + g    ) * AP_P + kb + 4]);
            af[3] = __float_as_uint(Ps[(r0 + 8 + g) * AP_P + kb + 4]);
#pragma unroll
            for (int nt = 0; nt < 16; nt++) {
                uint32 bf[2];
                bf[0] = __float_as_uint(Vs[(kb    ) * AV_P + nt*8 + g]);
                bf[1] = __float_as_uint(Vs[(kb + 4) * AV_P + nt*8 + g]);
                mma_tf32(oacc[nt], af, bf);
            }
        }
    }

    const float invA = 1.f / lA;
    const float invB = 1.f / lB;
    float* baseA = g_ctx + (size_t)(b*SEQ + q0 + r0 + g    ) * DM + h*HD;
    float* baseB = g_ctx + (size_t)(b*SEQ + q0 + r0 + 8 + g) * DM + h*HD;
#pragma unroll
    for (int nt = 0; nt < 16; nt++) {
        *(float2*)(baseA + nt*8 + 2*t) = make_float2(oacc[nt][0]*invA, oacc[nt][1]*invA);
        *(float2*)(baseB + nt*8 + 2*t) = make_float2(oacc[nt][2]*invB, oacc[nt][3]*invB);
    }
}

// ---------------------------------------------------------------------------
// Launch: strictly serial, stateless, static-smem GEMMs.
// ---------------------------------------------------------------------------
extern "C" void kernel_launch(void* const* d_in, const int* in_sizes, int n_in,
                              void* d_out, int out_size)
{
    (void)in_sizes; (void)n_in; (void)out_size;
    const float* x    = (const float*)d_in[0];
    const float* W_q  = (const float*)d_in[1];
    const float* W_dkv= (const float*)d_in[2];
    const float* W_uk = (const float*)d_in[3];
    const float* W_uv = (const float*)d_in[4];
    const float* W_o  = (const float*)d_in[5];
    const float* W_b  = (const float*)d_in[6];
    float* out = (float*)d_out;

    cudaFuncSetAttribute(attn_mma,
                         cudaFuncAttributeMaxDynamicSharedMemorySize,
                         ATTN_SMEM_BYTES);

    dim3 blk(256);
    tgemm_nt<0, 1><<<dim3(DL/128, TOK/64), blk>>>(x, W_dkv, nullptr, nullptr, TOK, DL, DM);
    tgemm_nt<1, 2><<<dim3(DM/128, TOK/128), blk>>>(x, W_q, nullptr, nullptr, TOK, DM, DM);
    tgemm_nt<23, 2><<<dim3(2*DM/128, TOK/128), blk>>>(nullptr, W_uk, W_uv, nullptr, TOK, DM, DL);
    attn_mma<<<dim3(SEQ/128, NB*NH), dim3(256), ATTN_SMEM_BYTES>>>();
    tgemm_nt<4, 2><<<dim3(DM/128, TOK/128), blk>>>(nullptr, W_o, W_b, out, TOK, DM, DM);
}